// round 7
// baseline (speedup 1.0000x reference)
#include <cuda_runtime.h>
#include <cuda_bf16.h>
#include <cstdint>

#define NC_MAX 1000000
#define NP_MAX 100000
#define DIM 64
#define H 4
#define DQK 8
#define DH 32
#define RPE 9
#define KVW 96
#define SCALE 0.35355339059327373f  // 8^-0.5

#define CH 128                     // children per tile
// per-4-child skew: 16B pad per 4-child group -> conflict-free micro-tile loads
#define XIDX4(child, c) (((child) << 6) + (((child) >> 2) << 2) + (c))
#define XS_FLOATS (CH * 64 + (CH / 4) * 4)     // 8320
#define WSV_FLOATS (64 * 64)                   // 4096
#define KS_FLOATS (CH * 33)                    // 4224
#define DYN_FLOATS (XS_FLOATS + WSV_FLOATS + KS_FLOATS)

// ---------------- packed f32x2 helpers ----------------
__device__ __forceinline__ unsigned long long pk2(float v) {
    unsigned long long r;
    asm("mov.b64 %0, {%1, %1};" : "=l"(r) : "f"(v));
    return r;
}
__device__ __forceinline__ void ffma2(unsigned long long& d, unsigned long long a,
                                      unsigned long long b) {
    asm("fma.rn.f32x2 %0, %1, %2, %0;" : "+l"(d) : "l"(a), "l"(b));
}
__device__ __forceinline__ void addf2(unsigned long long& d, unsigned long long a) {
    asm("add.rn.f32x2 %0, %0, %1;" : "+l"(d) : "l"(a));
}
__device__ __forceinline__ void mulf2(unsigned long long& d, unsigned long long a) {
    asm("mul.rn.f32x2 %0, %0, %1;" : "+l"(d) : "l"(a));
}
__device__ __forceinline__ float2 unpk(unsigned long long v) {
    float2 r;
    asm("mov.b64 {%0, %1}, %2;" : "=f"(r.x), "=f"(r.y) : "l"(v));
    return r;
}

// ---------------- device scratch ----------------
__device__ __align__(16) float g_qp[NP_MAX * DH];
__device__ __align__(16) float g_s[NP_MAX * H];
__device__ int g_idx[NC_MAX];
__device__ int g_is64;

// ---------------- index dtype detection ----------------
__global__ void detect_kernel(const unsigned int* __restrict__ raw, int nc) {
    __shared__ int found;
    if (threadIdx.x == 0) found = 0;
    __syncthreads();
    int limit = nc / 2; if (limit > 2048) limit = 2048;
    for (int i = threadIdx.x; i < limit; i += blockDim.x)
        if (raw[2 * i + 1] != 0u) found = 1;
    __syncthreads();
    if (threadIdx.x == 0) g_is64 = (found == 0) ? 1 : 0;
}

__global__ void cvt_index_kernel(const void* __restrict__ idxp, int nc) {
    int i = blockIdx.x * blockDim.x + threadIdx.x;
    if (i >= nc) return;
    if (g_is64) g_idx[i] = (int)((const long long*)idxp)[i];
    else        g_idx[i] = ((const int*)idxp)[i];
}

// ---------------- parent query projection ----------------
__global__ void __launch_bounds__(256, 2) qp_kernel(
    const float* __restrict__ x_parent, const float* __restrict__ wq,
    const float* __restrict__ bq, int np)
{
    const int t = threadIdx.x & 31;
    const int w = threadIdx.x >> 5;
    __shared__ __align__(16) float xs[8][64];

    float wr[64];
#pragma unroll
    for (int c = 0; c < 64; c++) wr[c] = wq[c * DH + t];
    const float b = bq[t];

    const int warps_total = gridDim.x * 8;
    for (int p = blockIdx.x * 8 + w; p < np; p += warps_total) {
        size_t base = (size_t)p * DIM;
        xs[w][t]      = x_parent[base + t];
        xs[w][t + 32] = x_parent[base + 32 + t];
        __syncwarp();
        float a0 = b, a1 = 0.f, a2 = 0.f, a3 = 0.f;
#pragma unroll
        for (int c = 0; c < 64; c += 4) {
            float4 xv = *(const float4*)&xs[w][c];
            a0 += xv.x * wr[c];
            a1 += xv.y * wr[c + 1];
            a2 += xv.z * wr[c + 2];
            a3 += xv.w * wr[c + 3];
        }
        g_qp[(size_t)p * DH + t] = ((a0 + a1) + (a2 + a3)) * SCALE;
        __syncwarp();
    }
}

// ---------------- fused: K-GEMM + compat/exp + V-GEMM + scatter ----------------
// Tile = 128 children, 256 threads, persistent grid-stride over tiles.
// One x staging feeds both the 32-col K projection and the 64-col V projection.
// out accumulates UNNORMALIZED sum(v*e); g_s accumulates sum(e); a final tiny
// kernel divides out by (s + 1e-16)  [division distributes over segment sum].
__global__ void __launch_bounds__(256, 2) fused_kernel(
    const float* __restrict__ x_child, const float* __restrict__ edge_attr,
    const float* __restrict__ wkv, const float* __restrict__ bkv,
    const float* __restrict__ wk_rpe, const float* __restrict__ bk_rpe,
    const float* __restrict__ wq_rpe, const float* __restrict__ bq_rpe,
    float* __restrict__ out, int nc, int ntiles)
{
    extern __shared__ __align__(16) float dsm[];
    float* xs  = dsm;                         // XS_FLOATS (skewed x tile)
    float* wsv = dsm + XS_FLOATS;             // [64][64] V weights
    float* ks  = wsv + WSV_FLOATS;            // [128][33] k tile

    __shared__ __align__(16) float wsk[64][32];
    __shared__ __align__(16) float wkr_s[RPE][32];
    __shared__ __align__(16) float wqr_s[RPE][32];
    __shared__ __align__(16) float bk_s[32];
    __shared__ __align__(16) float bq_s[32];
    __shared__ __align__(16) float eas[CH][12];
    __shared__ __align__(16) float es4[CH][4];
    __shared__ int pidx[CH];

    const int tid = threadIdx.x;
    const int cg = tid & 7;             // col group
    const int chb = (tid >> 3) * 4;     // 4-children base (0..124)
    const int hh = cg >> 1;             // head for V cols cg*8..+7
    const int xbase = chb * 64 + (chb >> 2) * 4;   // XIDX4(chb, 0)

    // one-time weight staging
    for (int k = tid; k < 64 * 32; k += 256) {
        int c = k >> 5, col = k & 31;
        wsk[c][col] = wkv[c * KVW + col];
    }
    for (int k = tid; k < 64 * 64; k += 256) {
        int c = k >> 6, j = k & 63;
        wsv[c * 64 + j] = wkv[c * KVW + DH + j];
    }
    for (int k = tid; k < RPE * 32; k += 256) {
        wkr_s[0][k] = wk_rpe[k];
        wqr_s[0][k] = wq_rpe[k];
    }
    if (tid < 32) {
        bk_s[tid] = bkv[tid] + bk_rpe[tid];
        bq_s[tid] = bq_rpe[tid];
    }
    const ulonglong2 bva = *(const ulonglong2*)&bkv[DH + cg * 8];
    const ulonglong2 bvb = *(const ulonglong2*)&bkv[DH + cg * 8 + 4];
    __syncthreads();

    for (int tile = blockIdx.x; tile < ntiles; tile += gridDim.x) {
        const int i0 = tile * CH;

        // ---- stage pidx, edge_attr, x ----
        if (tid < CH) {
            int i = i0 + tid;
            pidx[tid] = (i < nc) ? g_idx[i] : 0;
        }
        for (int k = tid; k < CH * RPE; k += 256) {
            int child = k / RPE, r = k - child * RPE;
            int i = i0 + child;
            eas[child][r] = (i < nc) ? edge_attr[(size_t)i * RPE + r] : 0.f;
        }
#pragma unroll
        for (int k = 0; k < 8; k++) {
            int idx = tid + 256 * k;          // 0..2047
            int child = idx >> 4, c4 = idx & 15;
            int i = i0 + child;
            float4 xv = make_float4(0.f, 0.f, 0.f, 0.f);
            if (i < nc) xv = *(const float4*)&x_child[(size_t)i * DIM + c4 * 4];
            *(float4*)&xs[XIDX4(child, c4 * 4)] = xv;
        }
        __syncthreads();

        // ---- K sub-pass: 4 children x 4 cols ----
        {
            unsigned long long acc[4][2];
#pragma unroll
            for (int j = 0; j < 4; j++) { acc[j][0] = 0ull; acc[j][1] = 0ull; }
#pragma unroll
            for (int cc = 0; cc < 64; cc += 4) {
                float4 xv[4];
#pragma unroll
                for (int j = 0; j < 4; j++)
                    xv[j] = *(const float4*)&xs[xbase + j * 64 + cc];
#pragma unroll
                for (int u = 0; u < 4; u++) {
                    ulonglong2 wp = *(const ulonglong2*)&wsk[cc + u][cg * 4];
#pragma unroll
                    for (int j = 0; j < 4; j++) {
                        unsigned long long xd = pk2(((const float*)&xv[j])[u]);
                        ffma2(acc[j][0], xd, wp.x);
                        ffma2(acc[j][1], xd, wp.y);
                    }
                }
            }
#pragma unroll
            for (int r = 0; r < RPE; r++) {
                ulonglong2 wp = *(const ulonglong2*)&wkr_s[r][cg * 4];
#pragma unroll
                for (int j = 0; j < 4; j++) {
                    unsigned long long xd = pk2(eas[chb + j][r]);
                    ffma2(acc[j][0], xd, wp.x);
                    ffma2(acc[j][1], xd, wp.y);
                }
            }
            // write k tile (+bias), stride 33
            const int col = cg * 4;
            const float b0 = bk_s[col], b1 = bk_s[col + 1];
            const float b2 = bk_s[col + 2], b3 = bk_s[col + 3];
#pragma unroll
            for (int j = 0; j < 4; j++) {
                float2 lo = unpk(acc[j][0]);
                float2 hi = unpk(acc[j][1]);
                float* kp = &ks[(chb + j) * 33 + col];
                kp[0] = lo.x + b0; kp[1] = lo.y + b1;
                kp[2] = hi.x + b2; kp[3] = hi.y + b3;
            }
        }

        // ---- V sub-pass: 4 children x 8 cols (kept in regs) ----
        unsigned long long vacc[4][4];
#pragma unroll
        for (int j = 0; j < 4; j++) {
            vacc[j][0] = bva.x; vacc[j][1] = bva.y;
            vacc[j][2] = bvb.x; vacc[j][3] = bvb.y;
        }
#pragma unroll
        for (int cc = 0; cc < 64; cc += 4) {
            float4 xv[4];
#pragma unroll
            for (int j = 0; j < 4; j++)
                xv[j] = *(const float4*)&xs[xbase + j * 64 + cc];
#pragma unroll
            for (int u = 0; u < 4; u++) {
                ulonglong2 wpa = *(const ulonglong2*)&wsv[(cc + u) * 64 + cg * 8];
                ulonglong2 wpb = *(const ulonglong2*)&wsv[(cc + u) * 64 + cg * 8 + 4];
#pragma unroll
                for (int j = 0; j < 4; j++) {
                    unsigned long long xd = pk2(((const float*)&xv[j])[u]);
                    ffma2(vacc[j][0], xd, wpa.x);
                    ffma2(vacc[j][1], xd, wpa.y);
                    ffma2(vacc[j][2], xd, wpb.x);
                    ffma2(vacc[j][3], xd, wpb.y);
                }
            }
        }
        __syncthreads();   // ks + eas stable; vacc in regs

        // ---- epilogue-e: 256 threads = 128 children x 2 halves ----
        {
            const int child = tid >> 1;
            const int half = tid & 1;
            const int i = i0 + child;
            if (i < nc) {
                const int p = pidx[child];
                const int col0 = half * 16;
                unsigned long long q[8];
                const unsigned long long* qpv =
                    (const unsigned long long*)&g_qp[(size_t)p * DH + col0];
                const unsigned long long* bqp =
                    (const unsigned long long*)&bq_s[col0];
#pragma unroll
                for (int j = 0; j < 8; j++) { q[j] = qpv[j]; addf2(q[j], bqp[j]); }
#pragma unroll
                for (int r = 0; r < RPE; r++) {
                    unsigned long long ed = pk2(eas[child][r]);
                    const unsigned long long* wqp =
                        (const unsigned long long*)&wqr_s[r][col0];
#pragma unroll
                    for (int j = 0; j < 8; j++) ffma2(q[j], ed, wqp[j]);
                }
                const float* krow = &ks[child * 33 + col0];
                float c0 = 0.f, c1 = 0.f;
#pragma unroll
                for (int j = 0; j < 4; j++) {
                    float2 qq = unpk(q[j]);
                    c0 += qq.x * krow[2 * j] + qq.y * krow[2 * j + 1];
                }
#pragma unroll
                for (int j = 4; j < 8; j++) {
                    float2 qq = unpk(q[j]);
                    c1 += qq.x * krow[2 * j] + qq.y * krow[2 * j + 1];
                }
                es4[child][half * 2 + 0] = __expf(c0);
                es4[child][half * 2 + 1] = __expf(c1);
            }
        }
        __syncthreads();

        // ---- scale v by e and scatter (unnormalized) ----
#pragma unroll
        for (int j = 0; j < 4; j++) {
            if (i0 + chb + j < nc) {
                unsigned long long ed = pk2(es4[chb + j][hh]);
                mulf2(vacc[j][0], ed); mulf2(vacc[j][1], ed);
                mulf2(vacc[j][2], ed); mulf2(vacc[j][3], ed);
                float2 r0 = unpk(vacc[j][0]), r1 = unpk(vacc[j][1]);
                float2 r2 = unpk(vacc[j][2]), r3 = unpk(vacc[j][3]);
                float* dst = out + (size_t)pidx[chb + j] * DIM + cg * 8;
                asm volatile("red.global.add.v4.f32 [%0], {%1,%2,%3,%4};"
                             :: "l"(dst), "f"(r0.x), "f"(r0.y), "f"(r1.x), "f"(r1.y)
                             : "memory");
                asm volatile("red.global.add.v4.f32 [%0], {%1,%2,%3,%4};"
                             :: "l"(dst + 4), "f"(r2.x), "f"(r2.y), "f"(r3.x), "f"(r3.y)
                             : "memory");
            }
        }
        // segment sums of e
        if (tid < CH) {
            int i = i0 + tid;
            if (i < nc) {
                float4 e4 = *(const float4*)&es4[tid][0];
                asm volatile("red.global.add.v4.f32 [%0], {%1,%2,%3,%4};"
                             :: "l"(g_s + (size_t)pidx[tid] * H),
                                "f"(e4.x), "f"(e4.y), "f"(e4.z), "f"(e4.w) : "memory");
            }
        }
        __syncthreads();   // protect shared buffers before next staging
    }
}

// ---------------- final normalize: out[p][j] /= (s[p][j>>4] + 1e-16) ----------------
__global__ void norm_kernel(float* __restrict__ out, int np) {
    int idx = blockIdx.x * blockDim.x + threadIdx.x;   // np*16 float4 groups
    if (idx >= np * 16) return;
    int p = idx >> 4, grp = idx & 15;
    float s = g_s[p * H + (grp >> 2)];
    float inv = 1.0f / (s + 1e-16f);
    float4 v = *(const float4*)&out[(size_t)p * DIM + grp * 4];
    v.x *= inv; v.y *= inv; v.z *= inv; v.w *= inv;
    *(float4*)&out[(size_t)p * DIM + grp * 4] = v;
}

// ---------------- launch ----------------
extern "C" void kernel_launch(void* const* d_in, const int* in_sizes, int n_in,
                              void* d_out, int out_size) {
    const float* x_child   = (const float*)d_in[0];
    const float* x_parent  = (const float*)d_in[1];
    const void*  index     = d_in[2];
    const float* edge_attr = (const float*)d_in[3];
    const float* wq        = (const float*)d_in[4];
    const float* bq        = (const float*)d_in[5];
    const float* wkv       = (const float*)d_in[6];
    const float* bkv       = (const float*)d_in[7];
    const float* wk_rpe    = (const float*)d_in[8];
    const float* bk_rpe    = (const float*)d_in[9];
    const float* wq_rpe    = (const float*)d_in[10];
    const float* bq_rpe    = (const float*)d_in[11];
    float* out = (float*)d_out;

    const int nc = in_sizes[0] / DIM;
    const int np = in_sizes[1] / DIM;

    const int DYN_BYTES = DYN_FLOATS * (int)sizeof(float);   // ~65KB
    static int attr_done = 0;
    if (!attr_done) {
        cudaFuncSetAttribute(fused_kernel,
                             cudaFuncAttributeMaxDynamicSharedMemorySize, DYN_BYTES);
        attr_done = 1;
    }

    cudaMemsetAsync(d_out, 0, (size_t)out_size * sizeof(float));
    void* s_addr = nullptr;
    cudaGetSymbolAddress(&s_addr, g_s);
    cudaMemsetAsync(s_addr, 0, (size_t)np * H * sizeof(float));

    detect_kernel<<<1, 256>>>((const unsigned int*)index, nc);
    cvt_index_kernel<<<(nc + 255) / 256, 256>>>(index, nc);

    qp_kernel<<<208, 256>>>(x_parent, wq, bq, np);

    const int ntiles = (nc + CH - 1) / CH;
    fused_kernel<<<296, 256, DYN_BYTES>>>(x_child, edge_attr, wkv, bkv,
                                          wk_rpe, bk_rpe, wq_rpe, bq_rpe,
                                          out, nc, ntiles);

    norm_kernel<<<(np * 16 + 255) / 256, 256>>>(out, np);
}